// round 4
// baseline (speedup 1.0000x reference)
#include <cuda_runtime.h>
#include <stdint.h>

#define NTHREADS 256

__device__ __forceinline__ float silu_f(float x) {
    // x * sigmoid(x); expf ~2ulp. x << 0 -> x/inf = -0, matches ref after quant.
    return x / (1.0f + expf(-x));
}

__device__ __forceinline__ int quant1(float a, float scale) {
    // jnp.clip(jnp.round(a / scale), -127, 127); jnp.round = half-to-even = rint
    int q = __float2int_rn(__fdiv_rn(a, scale));
    q = max(-127, min(127, q));
    return q;
}

// One CTA per token. d must equal 4*NTHREADS*D4PER. Act held in registers.
// OUT_FLOAT=true  : quantized values written as float32 (harness packed tuple to common f32 dtype)
// OUT_FLOAT=false : quantized values written as int8 bytes, scales as f32 after the int8 block
template <int D4PER, bool OUT_FLOAT>
__global__ __launch_bounds__(NTHREADS, 1)
void swiglu_quant_fast(const float* __restrict__ input,
                       const float* __restrict__ smooth_scale,
                       const int*   __restrict__ sorted_ids,
                       const int*   __restrict__ topk,
                       void*        __restrict__ qout,
                       float*       __restrict__ qscale,
                       int d)
{
    const int token = blockIdx.x;
    const int t     = threadIdx.x;

    const int sid = __ldg(sorted_ids + token);
    const int e   = __ldg(topk + token);

    const float4* gate = reinterpret_cast<const float4*>(input + (size_t)sid * (size_t)(2 * d));
    const float4* up   = gate + (d >> 2);
    const float4* ss   = reinterpret_cast<const float4*>(smooth_scale + (size_t)e * (size_t)d);

    float4 act[D4PER];
    float amax = 0.0f;

    #pragma unroll
    for (int k = 0; k < D4PER; k++) {
        const int i = t + k * NTHREADS;
        const float4 g = __ldg(gate + i);
        const float4 u = __ldg(up + i);
        const float4 s = __ldg(ss + i);
        float4 a;
        a.x = silu_f(g.x) * u.x * s.x;
        a.y = silu_f(g.y) * u.y * s.y;
        a.z = silu_f(g.z) * u.z * s.z;
        a.w = silu_f(g.w) * u.w * s.w;
        act[k] = a;
        amax = fmaxf(amax, fmaxf(fmaxf(fabsf(a.x), fabsf(a.y)),
                                 fmaxf(fabsf(a.z), fabsf(a.w))));
    }

    // Block amax: warp shuffle reduce, then every thread scans the 8 warp maxima.
    __shared__ float wmax[NTHREADS / 32];
    #pragma unroll
    for (int o = 16; o > 0; o >>= 1)
        amax = fmaxf(amax, __shfl_xor_sync(0xffffffffu, amax, o));
    if ((t & 31) == 0) wmax[t >> 5] = amax;
    __syncthreads();
    float bmax = wmax[0];
    #pragma unroll
    for (int w = 1; w < NTHREADS / 32; w++) bmax = fmaxf(bmax, wmax[w]);

    const float scale = (bmax > 0.0f) ? __fdiv_rn(bmax, 127.0f) : 1.0f;
    if (t == 0) qscale[token] = scale;

    if (OUT_FLOAT) {
        float4* orow = reinterpret_cast<float4*>((float*)qout + (size_t)token * (size_t)d);
        #pragma unroll
        for (int k = 0; k < D4PER; k++) {
            const int i = t + k * NTHREADS;
            const float4 a = act[k];
            float4 f;
            f.x = (float)quant1(a.x, scale);
            f.y = (float)quant1(a.y, scale);
            f.z = (float)quant1(a.z, scale);
            f.w = (float)quant1(a.w, scale);
            orow[i] = f;
        }
    } else {
        char4* orow = reinterpret_cast<char4*>((int8_t*)qout + (size_t)token * (size_t)d);
        #pragma unroll
        for (int k = 0; k < D4PER; k++) {
            const int i = t + k * NTHREADS;
            const float4 a = act[k];
            char4 c;
            c.x = (char)quant1(a.x, scale);
            c.y = (char)quant1(a.y, scale);
            c.z = (char)quant1(a.z, scale);
            c.w = (char)quant1(a.w, scale);
            orow[i] = c;
        }
    }
}

// Generic fallback for any d (smem-staged act), same dual output convention.
template <bool OUT_FLOAT>
__global__ __launch_bounds__(NTHREADS, 1)
void swiglu_quant_generic(const float* __restrict__ input,
                          const float* __restrict__ smooth_scale,
                          const int*   __restrict__ sorted_ids,
                          const int*   __restrict__ topk,
                          void*        __restrict__ qout,
                          float*       __restrict__ qscale,
                          int d)
{
    extern __shared__ float s_act[];
    const int token = blockIdx.x;
    const int t     = threadIdx.x;

    const int sid = __ldg(sorted_ids + token);
    const int e   = __ldg(topk + token);

    const float* gate = input + (size_t)sid * (size_t)(2 * d);
    const float* up   = gate + d;
    const float* ss   = smooth_scale + (size_t)e * (size_t)d;

    float amax = 0.0f;
    for (int j = t; j < d; j += NTHREADS) {
        float a = silu_f(__ldg(gate + j)) * __ldg(up + j) * __ldg(ss + j);
        s_act[j] = a;
        amax = fmaxf(amax, fabsf(a));
    }

    __shared__ float wmax[NTHREADS / 32];
    #pragma unroll
    for (int o = 16; o > 0; o >>= 1)
        amax = fmaxf(amax, __shfl_xor_sync(0xffffffffu, amax, o));
    if ((t & 31) == 0) wmax[t >> 5] = amax;
    __syncthreads();
    float bmax = wmax[0];
    #pragma unroll
    for (int w = 1; w < NTHREADS / 32; w++) bmax = fmaxf(bmax, wmax[w]);

    const float scale = (bmax > 0.0f) ? __fdiv_rn(bmax, 127.0f) : 1.0f;
    if (t == 0) qscale[token] = scale;

    if (OUT_FLOAT) {
        float* orow = (float*)qout + (size_t)token * (size_t)d;
        for (int j = t; j < d; j += NTHREADS)
            orow[j] = (float)quant1(s_act[j], scale);
    } else {
        int8_t* orow = (int8_t*)qout + (size_t)token * (size_t)d;
        for (int j = t; j < d; j += NTHREADS)
            orow[j] = (int8_t)quant1(s_act[j], scale);
    }
}

extern "C" void kernel_launch(void* const* d_in, const int* in_sizes, int n_in,
                              void* d_out, int out_size)
{
    const float* input        = (const float*)d_in[0];
    const float* smooth_scale = (const float*)d_in[1];
    const int*   sorted_ids   = (const int*)d_in[2];
    const int*   topk         = (const int*)d_in[3];

    const int N   = in_sizes[2];             // number of tokens (16384)
    const int fc1 = in_sizes[0] / N;         // 4096
    const int d   = fc1 / 2;                 // 2048

    // Discriminate output packing by out_size:
    //   float32 common dtype: out_size == N*d + N      (q as f32, then scales f32)
    //   int8/byte packing:    out_size == N*d + 4*N    (q as i8, then scales f32)
    const long long want_f32 = (long long)N * d + N;
    const bool out_float = ((long long)out_size == want_f32);

    void*  qout   = d_out;
    float* qscale = out_float
        ? ((float*)d_out + (size_t)N * (size_t)d)
        : (float*)((int8_t*)d_out + (size_t)N * (size_t)d);

    const int per = d / (4 * NTHREADS);      // float4s per thread per half (2 for d=2048)
    const bool fast = (d % (4 * NTHREADS) == 0) && per >= 1 && per <= 4;

    if (fast) {
        if (out_float) {
            switch (per) {
                case 1: swiglu_quant_fast<1, true><<<N, NTHREADS>>>(input, smooth_scale, sorted_ids, topk, qout, qscale, d); break;
                case 2: swiglu_quant_fast<2, true><<<N, NTHREADS>>>(input, smooth_scale, sorted_ids, topk, qout, qscale, d); break;
                case 3: swiglu_quant_fast<3, true><<<N, NTHREADS>>>(input, smooth_scale, sorted_ids, topk, qout, qscale, d); break;
                default: swiglu_quant_fast<4, true><<<N, NTHREADS>>>(input, smooth_scale, sorted_ids, topk, qout, qscale, d); break;
            }
        } else {
            switch (per) {
                case 1: swiglu_quant_fast<1, false><<<N, NTHREADS>>>(input, smooth_scale, sorted_ids, topk, qout, qscale, d); break;
                case 2: swiglu_quant_fast<2, false><<<N, NTHREADS>>>(input, smooth_scale, sorted_ids, topk, qout, qscale, d); break;
                case 3: swiglu_quant_fast<3, false><<<N, NTHREADS>>>(input, smooth_scale, sorted_ids, topk, qout, qscale, d); break;
                default: swiglu_quant_fast<4, false><<<N, NTHREADS>>>(input, smooth_scale, sorted_ids, topk, qout, qscale, d); break;
            }
        }
    } else {
        if (out_float)
            swiglu_quant_generic<true><<<N, NTHREADS, d * sizeof(float)>>>(input, smooth_scale, sorted_ids, topk, qout, qscale, d);
        else
            swiglu_quant_generic<false><<<N, NTHREADS, d * sizeof(float)>>>(input, smooth_scale, sorted_ids, topk, qout, qscale, d);
    }
}

// round 5
// speedup vs baseline: 1.2137x; 1.2137x over previous
#include <cuda_runtime.h>
#include <stdint.h>

#define NTHREADS 256

__device__ __forceinline__ float silu_fast(float x) {
    // x * sigmoid(x) via MUFU.EX2 + MUFU.RCP.
    // x >> 0: __expf(-x)=0 -> x/1. x << 0: denom huge -> __fdividef returns 0; quant -> 0 either way.
    return __fdividef(x, 1.0f + __expf(-x));
}

__device__ __forceinline__ int quant1(float a, float inv_scale) {
    // ref: clip(round(a / scale)); we multiply by 127/amax (one div per row, hoisted)
    int q = __float2int_rn(a * inv_scale);
    return max(-127, min(127, q));
}

// One CTA per token. d == 4*NTHREADS*D4PER. Act held in registers.
// OUT_FLOAT=true : quantized values written as float32 (tuple flattened to common f32 dtype)
template <int D4PER, bool OUT_FLOAT>
__global__ __launch_bounds__(NTHREADS, 1)
void swiglu_quant_fast(const float* __restrict__ input,
                       const float* __restrict__ smooth_scale,
                       const int*   __restrict__ sorted_ids,
                       const int*   __restrict__ topk,
                       void*        __restrict__ qout,
                       float*       __restrict__ qscale,
                       int d)
{
    const int token = blockIdx.x;
    const int t     = threadIdx.x;

    const int sid = __ldg(sorted_ids + token);
    const int e   = __ldg(topk + token);

    const float4* gate = reinterpret_cast<const float4*>(input + (size_t)sid * (size_t)(2 * d));
    const float4* up   = gate + (d >> 2);
    const float4* ss   = reinterpret_cast<const float4*>(smooth_scale + (size_t)e * (size_t)d);

    float4 act[D4PER];
    float amax = 0.0f;

    #pragma unroll
    for (int k = 0; k < D4PER; k++) {
        const int i = t + k * NTHREADS;
        const float4 g = __ldg(gate + i);
        const float4 u = __ldg(up + i);
        const float4 s = __ldg(ss + i);
        float4 a;
        a.x = silu_fast(g.x) * u.x * s.x;
        a.y = silu_fast(g.y) * u.y * s.y;
        a.z = silu_fast(g.z) * u.z * s.z;
        a.w = silu_fast(g.w) * u.w * s.w;
        act[k] = a;
        amax = fmaxf(amax, fmaxf(fmaxf(fabsf(a.x), fabsf(a.y)),
                                 fmaxf(fabsf(a.z), fabsf(a.w))));
    }

    // Block amax: warp shuffle reduce, then every thread scans the warp maxima.
    __shared__ float wmax[NTHREADS / 32];
    #pragma unroll
    for (int o = 16; o > 0; o >>= 1)
        amax = fmaxf(amax, __shfl_xor_sync(0xffffffffu, amax, o));
    if ((t & 31) == 0) wmax[t >> 5] = amax;
    __syncthreads();
    float bmax = wmax[0];
    #pragma unroll
    for (int w = 1; w < NTHREADS / 32; w++) bmax = fmaxf(bmax, wmax[w]);

    // Emitted scale matches the reference exactly (IEEE divide).
    const float scale     = (bmax > 0.0f) ? __fdiv_rn(bmax, 127.0f) : 1.0f;
    const float inv_scale = (bmax > 0.0f) ? __fdividef(127.0f, bmax) : 1.0f;
    if (t == 0) qscale[token] = scale;

    if (OUT_FLOAT) {
        float4* orow = reinterpret_cast<float4*>((float*)qout + (size_t)token * (size_t)d);
        #pragma unroll
        for (int k = 0; k < D4PER; k++) {
            const int i = t + k * NTHREADS;
            const float4 a = act[k];
            float4 f;
            f.x = (float)quant1(a.x, inv_scale);
            f.y = (float)quant1(a.y, inv_scale);
            f.z = (float)quant1(a.z, inv_scale);
            f.w = (float)quant1(a.w, inv_scale);
            __stcs(orow + i, f);   // streaming store: don't pollute L2 (output never re-read)
        }
    } else {
        char4* orow = reinterpret_cast<char4*>((int8_t*)qout + (size_t)token * (size_t)d);
        #pragma unroll
        for (int k = 0; k < D4PER; k++) {
            const int i = t + k * NTHREADS;
            const float4 a = act[k];
            char4 c;
            c.x = (char)quant1(a.x, inv_scale);
            c.y = (char)quant1(a.y, inv_scale);
            c.z = (char)quant1(a.z, inv_scale);
            c.w = (char)quant1(a.w, inv_scale);
            orow[i] = c;
        }
    }
}

// Generic fallback for any d (smem-staged act), same dual output convention.
template <bool OUT_FLOAT>
__global__ __launch_bounds__(NTHREADS, 1)
void swiglu_quant_generic(const float* __restrict__ input,
                          const float* __restrict__ smooth_scale,
                          const int*   __restrict__ sorted_ids,
                          const int*   __restrict__ topk,
                          void*        __restrict__ qout,
                          float*       __restrict__ qscale,
                          int d)
{
    extern __shared__ float s_act[];
    const int token = blockIdx.x;
    const int t     = threadIdx.x;

    const int sid = __ldg(sorted_ids + token);
    const int e   = __ldg(topk + token);

    const float* gate = input + (size_t)sid * (size_t)(2 * d);
    const float* up   = gate + d;
    const float* ss   = smooth_scale + (size_t)e * (size_t)d;

    float amax = 0.0f;
    for (int j = t; j < d; j += NTHREADS) {
        float a = silu_fast(__ldg(gate + j)) * __ldg(up + j) * __ldg(ss + j);
        s_act[j] = a;
        amax = fmaxf(amax, fabsf(a));
    }

    __shared__ float wmax[NTHREADS / 32];
    #pragma unroll
    for (int o = 16; o > 0; o >>= 1)
        amax = fmaxf(amax, __shfl_xor_sync(0xffffffffu, amax, o));
    if ((t & 31) == 0) wmax[t >> 5] = amax;
    __syncthreads();
    float bmax = wmax[0];
    #pragma unroll
    for (int w = 1; w < NTHREADS / 32; w++) bmax = fmaxf(bmax, wmax[w]);

    const float scale     = (bmax > 0.0f) ? __fdiv_rn(bmax, 127.0f) : 1.0f;
    const float inv_scale = (bmax > 0.0f) ? __fdividef(127.0f, bmax) : 1.0f;
    if (t == 0) qscale[token] = scale;

    if (OUT_FLOAT) {
        float* orow = (float*)qout + (size_t)token * (size_t)d;
        for (int j = t; j < d; j += NTHREADS)
            orow[j] = (float)quant1(s_act[j], inv_scale);
    } else {
        int8_t* orow = (int8_t*)qout + (size_t)token * (size_t)d;
        for (int j = t; j < d; j += NTHREADS)
            orow[j] = (int8_t)quant1(s_act[j], inv_scale);
    }
}

extern "C" void kernel_launch(void* const* d_in, const int* in_sizes, int n_in,
                              void* d_out, int out_size)
{
    const float* input        = (const float*)d_in[0];
    const float* smooth_scale = (const float*)d_in[1];
    const int*   sorted_ids   = (const int*)d_in[2];
    const int*   topk         = (const int*)d_in[3];

    const int N   = in_sizes[2];             // number of tokens (16384)
    const int fc1 = in_sizes[0] / N;         // 4096
    const int d   = fc1 / 2;                 // 2048

    // Output packing (discriminated by out_size; f32 common dtype confirmed in R3):
    //   float32 common dtype: out_size == N*d + N
    //   int8/byte packing:    out_size == N*d + 4*N
    const long long want_f32 = (long long)N * d + N;
    const bool out_float = ((long long)out_size == want_f32);

    void*  qout   = d_out;
    float* qscale = out_float
        ? ((float*)d_out + (size_t)N * (size_t)d)
        : (float*)((int8_t*)d_out + (size_t)N * (size_t)d);

    const int per = d / (4 * NTHREADS);      // float4s per thread per half (2 for d=2048)
    const bool fast = (d % (4 * NTHREADS) == 0) && per >= 1 && per <= 4;

    if (fast) {
        if (out_float) {
            switch (per) {
                case 1: swiglu_quant_fast<1, true><<<N, NTHREADS>>>(input, smooth_scale, sorted_ids, topk, qout, qscale, d); break;
                case 2: swiglu_quant_fast<2, true><<<N, NTHREADS>>>(input, smooth_scale, sorted_ids, topk, qout, qscale, d); break;
                case 3: swiglu_quant_fast<3, true><<<N, NTHREADS>>>(input, smooth_scale, sorted_ids, topk, qout, qscale, d); break;
                default: swiglu_quant_fast<4, true><<<N, NTHREADS>>>(input, smooth_scale, sorted_ids, topk, qout, qscale, d); break;
            }
        } else {
            switch (per) {
                case 1: swiglu_quant_fast<1, false><<<N, NTHREADS>>>(input, smooth_scale, sorted_ids, topk, qout, qscale, d); break;
                case 2: swiglu_quant_fast<2, false><<<N, NTHREADS>>>(input, smooth_scale, sorted_ids, topk, qout, qscale, d); break;
                case 3: swiglu_quant_fast<3, false><<<N, NTHREADS>>>(input, smooth_scale, sorted_ids, topk, qout, qscale, d); break;
                default: swiglu_quant_fast<4, false><<<N, NTHREADS>>>(input, smooth_scale, sorted_ids, topk, qout, qscale, d); break;
            }
        }
    } else {
        if (out_float)
            swiglu_quant_generic<true><<<N, NTHREADS, d * sizeof(float)>>>(input, smooth_scale, sorted_ids, topk, qout, qscale, d);
        else
            swiglu_quant_generic<false><<<N, NTHREADS, d * sizeof(float)>>>(input, smooth_scale, sorted_ids, topk, qout, qscale, d);
    }
}